// round 5
// baseline (speedup 1.0000x reference)
#include <cuda_runtime.h>
#include <cstdint>

#define NN 50000
#define EE 800000
#define RR 8
#define HD 128
#define NG 2                      // graphs
#define NT ((NN + 127) / 128)     // 391 dst tiles
#define NB (NG * NT * RR)         // 6256 buckets

#define SA 132                    // S row stride (words): A-frag conflict-free
#define SBW 136                   // Wb row stride (words): B-frag conflict-free
#define AGG_SMEM ((128 * SA + 32 * SBW) * 4)   // 67584 + 17408 = 84992 B

// ---------------- scratch (device globals; no allocation allowed) ----------
__device__ float    g_denom[NG * NN];
__device__ float    g_wq[NG * RR * HD];
__device__ float    g_wk[NG * RR * HD];
__device__ float    g_qi[NG * NN * RR];
__device__ float    g_kj[NG * NN * RR];
__device__ uint32_t g_cnt[NB];
__device__ uint32_t g_off[NB + 1];
__device__ uint32_t g_cur[NB];
__device__ uint2    g_es[(size_t)NG * EE];   // .x = src | (loc<<16), .y = ex bits

__device__ __forceinline__ uint32_t f2tf32(float f) {
    uint32_t u;
    asm("cvt.rna.tf32.f32 %0, %1;" : "=r"(u) : "f"(f));
    return u;
}

// ---------------- zero denom + bucket counts --------------------------------
__global__ void prep_kernel() {
    int i = blockIdx.x * blockDim.x + threadIdx.x;
    int stride = gridDim.x * blockDim.x;
    for (int j = i; j < NG * NN; j += stride) g_denom[j] = 0.f;
    for (int j = i; j < NB; j += stride) g_cnt[j] = 0u;
}

// ---------------- Wq[r] = W_r @ q, Wk[r] = W_r @ k --------------------------
__global__ void wqwk_kernel(const float* __restrict__ W1, const float* __restrict__ q1,
                            const float* __restrict__ k1,
                            const float* __restrict__ W2, const float* __restrict__ q2,
                            const float* __restrict__ k2) {
    int graph = blockIdx.y;
    const float* W = graph ? W2 : W1;
    const float* q = graph ? q2 : q1;
    const float* k = graph ? k2 : k1;
    int w = (blockIdx.x * blockDim.x + threadIdx.x) >> 5;
    int lane = threadIdx.x & 31;
    if (w >= RR * HD) return;
    const float* row = W + (size_t)w * HD;
    float sq = 0.f, sk = 0.f;
#pragma unroll
    for (int j = lane; j < HD; j += 32) {
        float wv = row[j];
        sq += wv * q[j];
        sk += wv * k[j];
    }
#pragma unroll
    for (int o = 16; o; o >>= 1) {
        sq += __shfl_xor_sync(0xffffffffu, sq, o);
        sk += __shfl_xor_sync(0xffffffffu, sk, o);
    }
    if (lane == 0) {
        g_wq[graph * RR * HD + w] = sq;
        g_wk[graph * RR * HD + w] = sk;
    }
}

// ---------------- per-node logit tables: qi[n][r], kj[n][r] -----------------
__global__ void table_kernel(const float* __restrict__ x1,
                             const float* __restrict__ x2) {
    int graph = blockIdx.y;
    const float* x = graph ? x2 : x1;
    int n = (blockIdx.x * blockDim.x + threadIdx.x) >> 5;
    if (n >= NN) return;
    int lane = threadIdx.x & 31;
    float4 xv = ((const float4*)x)[(size_t)n * 32 + lane];
    const float4* wq4 = (const float4*)(g_wq + graph * RR * HD);
    const float4* wk4 = (const float4*)(g_wk + graph * RR * HD);
#pragma unroll
    for (int r = 0; r < RR; r++) {
        float4 wq = wq4[r * 32 + lane];
        float4 wk = wk4[r * 32 + lane];
        float sq = xv.x * wq.x + xv.y * wq.y + xv.z * wq.z + xv.w * wq.w;
        float sk = xv.x * wk.x + xv.y * wk.y + xv.z * wk.z + xv.w * wk.w;
#pragma unroll
        for (int o = 16; o; o >>= 1) {
            sq += __shfl_xor_sync(0xffffffffu, sq, o);
            sk += __shfl_xor_sync(0xffffffffu, sk, o);
        }
        if (lane == 0) {
            g_qi[(graph * NN + n) * RR + r] = sq;
            g_kj[(graph * NN + n) * RR + r] = sk;
        }
    }
}

// ---------------- histogram over (dst-tile, relation) buckets ---------------
__global__ void hist_kernel(const int* __restrict__ ei1, const int* __restrict__ et1,
                            const int* __restrict__ ei2, const int* __restrict__ et2) {
    __shared__ uint32_t h[NT * RR];
    int graph = blockIdx.y;
    const int* ei = graph ? ei2 : ei1;
    const int* et = graph ? et2 : et1;
    for (int i = threadIdx.x; i < NT * RR; i += 256) h[i] = 0u;
    __syncthreads();
    int base = blockIdx.x * 4096;
#pragma unroll
    for (int i = 0; i < 16; i++) {
        int e = base + threadIdx.x + i * 256;
        if (e < EE) {
            int dst = __ldg(ei + EE + e);
            int r = __ldg(et + e);
            atomicAdd(&h[(dst >> 7) * RR + r], 1u);
        }
    }
    __syncthreads();
    uint32_t* cnt = g_cnt + graph * NT * RR;
    for (int i = threadIdx.x; i < NT * RR; i += 256)
        if (h[i]) atomicAdd(&cnt[i], h[i]);
}

// ---------------- exclusive scan over NB buckets (single block) -------------
__global__ void scan_kernel() {
    __shared__ uint32_t part[256];
    const int per = (NB + 255) / 256;   // 25
    int t = threadIdx.x;
    uint32_t loc[per];
    uint32_t s = 0;
#pragma unroll
    for (int i = 0; i < per; i++) {
        int idx = t * per + i;
        uint32_t v = (idx < NB) ? g_cnt[idx] : 0u;
        loc[i] = s;
        s += v;
    }
    part[t] = s;
    __syncthreads();
    for (int o = 1; o < 256; o <<= 1) {
        uint32_t v = (t >= o) ? part[t - o] : 0u;
        __syncthreads();
        part[t] += v;
        __syncthreads();
    }
    uint32_t base = t ? part[t - 1] : 0u;
#pragma unroll
    for (int i = 0; i < per; i++) {
        int idx = t * per + i;
        if (idx < NB) {
            uint32_t off = base + loc[i];
            g_off[idx] = off;
            g_cur[idx] = off;
        }
    }
    if (t == 255) g_off[NB] = part[255];
}

// ---------------- reorder edges into buckets + denom + ex -------------------
__global__ void reorder_kernel(const int* __restrict__ ei1, const int* __restrict__ et1,
                               const int* __restrict__ ei2, const int* __restrict__ et2) {
    int graph = blockIdx.y;
    const int* ei = graph ? ei2 : ei1;
    const int* et = graph ? et2 : et1;
    int e = blockIdx.x * 256 + threadIdx.x;
    if (e >= EE) return;
    int src = __ldg(ei + e);
    int dst = __ldg(ei + EE + e);
    int r = __ldg(et + e);
    float al = g_qi[(graph * NN + dst) * RR + r] + g_kj[(graph * NN + src) * RR + r];
    al = al > 0.f ? al : 0.2f * al;          // leaky_relu
    float ex = __expf(al);                   // alpha ~ O(1): no max-shift
    atomicAdd(&g_denom[graph * NN + dst], ex);
    uint32_t key = graph * NT * RR + (dst >> 7) * RR + r;
    uint32_t p = atomicAdd(&g_cur[key], 1u);
    g_es[p] = make_uint2((uint32_t)src | ((uint32_t)(dst & 127) << 16),
                         __float_as_uint(ex));
}

// ---------------- fused aggregate + GEMM + epilogue -------------------------
// Block = (dst-tile, graph). For each r: S = sum(ex * x[src]) in smem
// (conflict-free scalar atomics), cvt tf32 in place, MMA S @ W_r into regs.
__global__ __launch_bounds__(256, 2)
void agg_gemm(const float* __restrict__ x1, const float* __restrict__ x2,
              const float* __restrict__ W1, const float* __restrict__ W2,
              const float* __restrict__ b1, const float* __restrict__ b2,
              float* __restrict__ out) {
    extern __shared__ uint32_t sm[];
    float* S = (float*)sm;                  // [128][SA]
    uint32_t* Su = sm;                      // same storage, tf32 bits after cvt
    uint32_t* Wb = sm + 128 * SA;           // [32][SBW]

    int graph = blockIdx.y;
    int tile = blockIdx.x;
    const float* x = graph ? x2 : x1;
    const float* W = graph ? W2 : W1;
    const float* bias = graph ? b2 : b1;
    int m0 = tile * 128;
    int tid = threadIdx.x, wid = tid >> 5, lane = tid & 31;
    int warpM = wid >> 1, warpN = wid & 1;
    int g = lane >> 2, t = lane & 3;

    float acc[2][8][4];
#pragma unroll
    for (int mt = 0; mt < 2; mt++)
#pragma unroll
        for (int nt = 0; nt < 8; nt++)
#pragma unroll
            for (int c = 0; c < 4; c++) acc[mt][nt][c] = 0.f;

    for (int r = 0; r < RR; r++) {
        // zero S (flat, incl. padding)
        float4 z = make_float4(0.f, 0.f, 0.f, 0.f);
        for (int i = tid; i < 128 * SA / 4; i += 256) ((float4*)S)[i] = z;
        __syncthreads();

        // accumulate edges of this (tile, r) bucket
        uint32_t key = graph * NT * RR + tile * RR + r;
        uint32_t beg = g_off[key], end = g_off[key + 1];
        for (uint32_t e = beg + wid; e < end; e += 8) {
            uint2 pk = g_es[e];
            int src = pk.x & 0xffff;
            int loc = (pk.x >> 16) & 0x7f;
            float ex = __uint_as_float(pk.y);
            const float* xr = x + (size_t)src * HD;
            float* Sp = &S[loc * SA];
#pragma unroll
            for (int c = 0; c < 4; c++) {
                int col = c * 32 + lane;            // conflict-free banks
                atomicAdd(Sp + col, ex * __ldg(xr + col));
            }
        }
        __syncthreads();

        // in-place fp32 -> tf32
        for (int i = tid; i < 128 * SA; i += 256) Su[i] = f2tf32(S[i]);
        __syncthreads();

        // MMA: acc += S @ W_r
        const float* Wr = W + (size_t)r * HD * HD;
        for (int kc = 0; kc < HD; kc += 32) {
            // load W chunk [32 k-rows][128 n-cols] with cvt
            for (int i = tid; i < 32 * 32; i += 256) {
                int row = i >> 5, c4 = i & 31;
                float4 v = ((const float4*)Wr)[(size_t)(kc + row) * 32 + c4];
                uint4 u = make_uint4(f2tf32(v.x), f2tf32(v.y), f2tf32(v.z), f2tf32(v.w));
                *(uint4*)&Wb[row * SBW + c4 * 4] = u;
            }
            __syncthreads();
#pragma unroll
            for (int kk = 0; kk < 32; kk += 8) {
                int kbase = kc + kk;
                uint32_t a[2][4];
#pragma unroll
                for (int mt = 0; mt < 2; mt++) {
                    int rb = warpM * 32 + mt * 16 + g;
                    a[mt][0] = Su[rb * SA + kbase + t];
                    a[mt][1] = Su[(rb + 8) * SA + kbase + t];
                    a[mt][2] = Su[rb * SA + kbase + t + 4];
                    a[mt][3] = Su[(rb + 8) * SA + kbase + t + 4];
                }
#pragma unroll
                for (int nt = 0; nt < 8; nt++) {
                    int col = warpN * 64 + nt * 8 + g;
                    uint32_t b0 = Wb[(kk + t) * SBW + col];
                    uint32_t b1v = Wb[(kk + t + 4) * SBW + col];
#pragma unroll
                    for (int mt = 0; mt < 2; mt++) {
                        asm volatile(
                            "mma.sync.aligned.m16n8k8.row.col.f32.tf32.tf32.f32 "
                            "{%0,%1,%2,%3}, {%4,%5,%6,%7}, {%8,%9}, {%0,%1,%2,%3};"
                            : "+f"(acc[mt][nt][0]), "+f"(acc[mt][nt][1]),
                              "+f"(acc[mt][nt][2]), "+f"(acc[mt][nt][3])
                            : "r"(a[mt][0]), "r"(a[mt][1]), "r"(a[mt][2]), "r"(a[mt][3]),
                              "r"(b0), "r"(b1v));
                    }
                }
            }
            __syncthreads();
        }
    }

    // epilogue: out = relu(acc / denom + bias)
#pragma unroll
    for (int mt = 0; mt < 2; mt++) {
        int row0 = m0 + warpM * 32 + mt * 16 + g;
        float inv0 = 0.f, inv8 = 0.f;
        if (row0 < NN)     inv0 = 1.0f / (g_denom[graph * NN + row0] + 1e-16f);
        if (row0 + 8 < NN) inv8 = 1.0f / (g_denom[graph * NN + row0 + 8] + 1e-16f);
#pragma unroll
        for (int nt = 0; nt < 8; nt++) {
            int col = warpN * 64 + nt * 8 + t * 2;
            float bb0 = __ldg(bias + col), bb1 = __ldg(bias + col + 1);
            if (row0 < NN) {
                float2 v;
                v.x = fmaxf(acc[mt][nt][0] * inv0 + bb0, 0.f);
                v.y = fmaxf(acc[mt][nt][1] * inv0 + bb1, 0.f);
                *(float2*)&out[((size_t)graph * NN + row0) * HD + col] = v;
            }
            if (row0 + 8 < NN) {
                float2 v;
                v.x = fmaxf(acc[mt][nt][2] * inv8 + bb0, 0.f);
                v.y = fmaxf(acc[mt][nt][3] * inv8 + bb1, 0.f);
                *(float2*)&out[((size_t)graph * NN + row0 + 8) * HD + col] = v;
            }
        }
    }
}

// ---------------- driver ----------------------------------------------------
extern "C" void kernel_launch(void* const* d_in, const int* in_sizes, int n_in,
                              void* d_out, int out_size) {
    const float* x1  = (const float*)d_in[0];
    const int*   ei1 = (const int*)d_in[1];
    const int*   et1 = (const int*)d_in[2];
    const float* x2  = (const float*)d_in[3];
    const int*   ei2 = (const int*)d_in[4];
    const int*   et2 = (const int*)d_in[5];
    const float* W1  = (const float*)d_in[6];
    const float* q1  = (const float*)d_in[7];
    const float* k1  = (const float*)d_in[8];
    const float* b1  = (const float*)d_in[9];
    const float* W2  = (const float*)d_in[10];
    const float* q2  = (const float*)d_in[11];
    const float* k2  = (const float*)d_in[12];
    const float* b2  = (const float*)d_in[13];
    float* out = (float*)d_out;

    cudaFuncSetAttribute(agg_gemm, cudaFuncAttributeMaxDynamicSharedMemorySize,
                         AGG_SMEM);

    prep_kernel<<<256, 256>>>();
    wqwk_kernel<<<dim3((RR * HD) / 8, NG), 256>>>(W1, q1, k1, W2, q2, k2);
    table_kernel<<<dim3((NN + 7) / 8, NG), 256>>>(x1, x2);
    hist_kernel<<<dim3((EE + 4095) / 4096, NG), 256>>>(ei1, et1, ei2, et2);
    scan_kernel<<<1, 256>>>();
    reorder_kernel<<<dim3((EE + 255) / 256, NG), 256>>>(ei1, et1, ei2, et2);
    agg_gemm<<<dim3(NT, NG), 256, AGG_SMEM>>>(x1, x2, W1, W2, b1, b2, out);
}

// round 6
// speedup vs baseline: 1.7694x; 1.7694x over previous
#include <cuda_runtime.h>
#include <cstdint>

#define NN 50000
#define EE 800000
#define RR 8
#define HD 128
#define NG 2                      // graphs
#define NT ((NN + 127) / 128)     // 391 src tiles
#define NB (NG * NT * RR)         // 6256 buckets

#define SA 132                    // A/xt tile row stride (words)
#define SBW 132                   // W chunk row stride (words)
#define FUSED_SMEM ((128 * SA + 32 * SBW) * 4)   // 84480 B -> 2 CTAs/SM

// ---------------- scratch (device globals; no allocation allowed) ----------
__device__ float    g_acc[(size_t)NG * NN * HD];   // 51.2 MB aggregation
__device__ float    g_denom[NG * NN];
__device__ float    g_wq[NG * RR * HD];
__device__ float    g_wk[NG * RR * HD];
__device__ float    g_qi[NG * NN * RR];
__device__ float    g_kj[NG * NN * RR];
__device__ uint32_t g_cnt[NB];
__device__ uint32_t g_off[NB + 1];
__device__ uint32_t g_cur[NB];
__device__ uint2    g_es[(size_t)NG * EE];  // .x = dst | (src&127)<<16, .y = ex

__device__ __forceinline__ uint32_t f2tf32(float f) {
    uint32_t u;
    asm("cvt.rna.tf32.f32 %0, %1;" : "=r"(u) : "f"(f));
    return u;
}

// ---------------- zero acc + denom + bucket counts --------------------------
__global__ void prep_kernel() {
    int i = blockIdx.x * blockDim.x + threadIdx.x;
    int stride = gridDim.x * blockDim.x;
    float4 z = make_float4(0.f, 0.f, 0.f, 0.f);
    float4* a4 = (float4*)g_acc;
    const int na4 = NG * NN * HD / 4;
    for (int j = i; j < na4; j += stride) a4[j] = z;
    for (int j = i; j < NG * NN; j += stride) g_denom[j] = 0.f;
    for (int j = i; j < NB; j += stride) g_cnt[j] = 0u;
}

// ---------------- Wq[r] = W_r @ q, Wk[r] = W_r @ k --------------------------
__global__ void wqwk_kernel(const float* __restrict__ W1, const float* __restrict__ q1,
                            const float* __restrict__ k1,
                            const float* __restrict__ W2, const float* __restrict__ q2,
                            const float* __restrict__ k2) {
    int graph = blockIdx.y;
    const float* W = graph ? W2 : W1;
    const float* q = graph ? q2 : q1;
    const float* k = graph ? k2 : k1;
    int w = (blockIdx.x * blockDim.x + threadIdx.x) >> 5;
    int lane = threadIdx.x & 31;
    if (w >= RR * HD) return;
    const float* row = W + (size_t)w * HD;
    float sq = 0.f, sk = 0.f;
#pragma unroll
    for (int j = lane; j < HD; j += 32) {
        float wv = row[j];
        sq += wv * q[j];
        sk += wv * k[j];
    }
#pragma unroll
    for (int o = 16; o; o >>= 1) {
        sq += __shfl_xor_sync(0xffffffffu, sq, o);
        sk += __shfl_xor_sync(0xffffffffu, sk, o);
    }
    if (lane == 0) {
        g_wq[graph * RR * HD + w] = sq;
        g_wk[graph * RR * HD + w] = sk;
    }
}

// ---------------- per-node logit tables: qi[n][r], kj[n][r] -----------------
__global__ void table_kernel(const float* __restrict__ x1,
                             const float* __restrict__ x2) {
    int graph = blockIdx.y;
    const float* x = graph ? x2 : x1;
    int n = (blockIdx.x * blockDim.x + threadIdx.x) >> 5;
    if (n >= NN) return;
    int lane = threadIdx.x & 31;
    float4 xv = ((const float4*)x)[(size_t)n * 32 + lane];
    const float4* wq4 = (const float4*)(g_wq + graph * RR * HD);
    const float4* wk4 = (const float4*)(g_wk + graph * RR * HD);
#pragma unroll
    for (int r = 0; r < RR; r++) {
        float4 wq = wq4[r * 32 + lane];
        float4 wk = wk4[r * 32 + lane];
        float sq = xv.x * wq.x + xv.y * wq.y + xv.z * wq.z + xv.w * wq.w;
        float sk = xv.x * wk.x + xv.y * wk.y + xv.z * wk.z + xv.w * wk.w;
#pragma unroll
        for (int o = 16; o; o >>= 1) {
            sq += __shfl_xor_sync(0xffffffffu, sq, o);
            sk += __shfl_xor_sync(0xffffffffu, sk, o);
        }
        if (lane == 0) {
            g_qi[(graph * NN + n) * RR + r] = sq;
            g_kj[(graph * NN + n) * RR + r] = sk;
        }
    }
}

// ---------------- histogram over (src-tile, relation) buckets ---------------
__global__ void hist_kernel(const int* __restrict__ ei1, const int* __restrict__ et1,
                            const int* __restrict__ ei2, const int* __restrict__ et2) {
    __shared__ uint32_t h[NT * RR];
    int graph = blockIdx.y;
    const int* ei = graph ? ei2 : ei1;
    const int* et = graph ? et2 : et1;
    for (int i = threadIdx.x; i < NT * RR; i += 256) h[i] = 0u;
    __syncthreads();
    int base = blockIdx.x * 4096;
#pragma unroll
    for (int i = 0; i < 16; i++) {
        int e = base + threadIdx.x + i * 256;
        if (e < EE) {
            int src = __ldg(ei + e);
            int r = __ldg(et + e);
            atomicAdd(&h[(src >> 7) * RR + r], 1u);
        }
    }
    __syncthreads();
    uint32_t* cnt = g_cnt + graph * NT * RR;
    for (int i = threadIdx.x; i < NT * RR; i += 256)
        if (h[i]) atomicAdd(&cnt[i], h[i]);
}

// ---------------- exclusive scan over NB buckets (single block) -------------
__global__ void scan_kernel() {
    __shared__ uint32_t part[256];
    const int per = (NB + 255) / 256;   // 25
    int t = threadIdx.x;
    uint32_t loc[per];
    uint32_t s = 0;
#pragma unroll
    for (int i = 0; i < per; i++) {
        int idx = t * per + i;
        uint32_t v = (idx < NB) ? g_cnt[idx] : 0u;
        loc[i] = s;
        s += v;
    }
    part[t] = s;
    __syncthreads();
    for (int o = 1; o < 256; o <<= 1) {
        uint32_t v = (t >= o) ? part[t - o] : 0u;
        __syncthreads();
        part[t] += v;
        __syncthreads();
    }
    uint32_t base = t ? part[t - 1] : 0u;
#pragma unroll
    for (int i = 0; i < per; i++) {
        int idx = t * per + i;
        if (idx < NB) {
            uint32_t off = base + loc[i];
            g_off[idx] = off;
            g_cur[idx] = off;
        }
    }
    if (t == 255) g_off[NB] = part[255];
}

// ---------------- reorder edges into src buckets + denom + ex ---------------
__global__ void reorder_kernel(const int* __restrict__ ei1, const int* __restrict__ et1,
                               const int* __restrict__ ei2, const int* __restrict__ et2) {
    int graph = blockIdx.y;
    const int* ei = graph ? ei2 : ei1;
    const int* et = graph ? et2 : et1;
    int e = blockIdx.x * 256 + threadIdx.x;
    if (e >= EE) return;
    int src = __ldg(ei + e);
    int dst = __ldg(ei + EE + e);
    int r = __ldg(et + e);
    float al = g_qi[(graph * NN + dst) * RR + r] + g_kj[(graph * NN + src) * RR + r];
    al = al > 0.f ? al : 0.2f * al;          // leaky_relu
    float ex = __expf(al);                   // alpha ~ O(1): no max-shift
    atomicAdd(&g_denom[graph * NN + dst], ex);
    uint32_t key = (graph * NT + (src >> 7)) * RR + r;
    uint32_t p = atomicAdd(&g_cur[key], 1u);
    g_es[p] = make_uint2((uint32_t)dst | ((uint32_t)(src & 127) << 16),
                         __float_as_uint(ex));
}

// ---------------- fused transform + scatter ---------------------------------
// CTA = (src-tile, r, graph). GEMM xt = x[tile] @ W_r (tf32 mma), write tile
// to smem (reusing A buffer), then scatter ex * xt[row] via red.global.
__global__ __launch_bounds__(256, 2)
void xform_scatter(const float* __restrict__ x1, const float* __restrict__ x2,
                   const float* __restrict__ W1, const float* __restrict__ W2) {
    extern __shared__ uint32_t sm[];
    uint32_t* As = sm;                  // [128][SA] tf32 bits; reused as xt fp32
    float* XS = (float*)sm;
    uint32_t* Wb = sm + 128 * SA;       // [32][SBW]

    int graph = blockIdx.z;
    int r = blockIdx.y;
    int tile = blockIdx.x;
    const float* x = graph ? x2 : x1;
    const float* Wr = (graph ? W2 : W1) + (size_t)r * HD * HD;
    int m0 = tile * 128;
    int tid = threadIdx.x, wid = tid >> 5, lane = tid & 31;
    int warpM = wid >> 1, warpN = wid & 1;
    int g = lane >> 2, t = lane & 3;

    // load A tile once (fp32 -> tf32)
    for (int idx = tid; idx < 128 * 32; idx += 256) {
        int row = idx >> 5, c4 = idx & 31;
        int gm = m0 + row;
        float4 v = make_float4(0.f, 0.f, 0.f, 0.f);
        if (gm < NN) v = ((const float4*)x)[(size_t)gm * 32 + c4];
        uint4 u = make_uint4(f2tf32(v.x), f2tf32(v.y), f2tf32(v.z), f2tf32(v.w));
        *(uint4*)&As[row * SA + c4 * 4] = u;
    }

    float acc[2][8][4];
#pragma unroll
    for (int mt = 0; mt < 2; mt++)
#pragma unroll
        for (int nt = 0; nt < 8; nt++)
#pragma unroll
            for (int c = 0; c < 4; c++) acc[mt][nt][c] = 0.f;

    for (int kc = 0; kc < HD; kc += 32) {
        __syncthreads();
        // load W chunk [32 k-rows][128 n-cols] with cvt
        for (int i = tid; i < 32 * 32; i += 256) {
            int row = i >> 5, c4 = i & 31;
            float4 v = ((const float4*)Wr)[(size_t)(kc + row) * 32 + c4];
            uint4 u = make_uint4(f2tf32(v.x), f2tf32(v.y), f2tf32(v.z), f2tf32(v.w));
            *(uint4*)&Wb[row * SBW + c4 * 4] = u;
        }
        __syncthreads();
#pragma unroll
        for (int kk = 0; kk < 32; kk += 8) {
            int kbase = kc + kk;
            uint32_t a[2][4];
#pragma unroll
            for (int mt = 0; mt < 2; mt++) {
                int rb = warpM * 32 + mt * 16 + g;
                a[mt][0] = As[rb * SA + kbase + t];
                a[mt][1] = As[(rb + 8) * SA + kbase + t];
                a[mt][2] = As[rb * SA + kbase + t + 4];
                a[mt][3] = As[(rb + 8) * SA + kbase + t + 4];
            }
#pragma unroll
            for (int nt = 0; nt < 8; nt++) {
                int col = warpN * 64 + nt * 8 + g;
                uint32_t b0 = Wb[(kk + t) * SBW + col];
                uint32_t b1v = Wb[(kk + t + 4) * SBW + col];
#pragma unroll
                for (int mt = 0; mt < 2; mt++) {
                    asm volatile(
                        "mma.sync.aligned.m16n8k8.row.col.f32.tf32.tf32.f32 "
                        "{%0,%1,%2,%3}, {%4,%5,%6,%7}, {%8,%9}, {%0,%1,%2,%3};"
                        : "+f"(acc[mt][nt][0]), "+f"(acc[mt][nt][1]),
                          "+f"(acc[mt][nt][2]), "+f"(acc[mt][nt][3])
                        : "r"(a[mt][0]), "r"(a[mt][1]), "r"(a[mt][2]), "r"(a[mt][3]),
                          "r"(b0), "r"(b1v));
                }
            }
        }
    }
    __syncthreads();   // all A fragments consumed — safe to overwrite with xt

    // write xt tile (fp32) into smem, layout [row][col] stride SA
#pragma unroll
    for (int mt = 0; mt < 2; mt++) {
        int row0 = warpM * 32 + mt * 16 + g;
#pragma unroll
        for (int nt = 0; nt < 8; nt++) {
            int col = warpN * 64 + nt * 8 + t * 2;
            *(float2*)&XS[row0 * SA + col] = make_float2(acc[mt][nt][0], acc[mt][nt][1]);
            *(float2*)&XS[(row0 + 8) * SA + col] = make_float2(acc[mt][nt][2], acc[mt][nt][3]);
        }
    }
    __syncthreads();

    // scatter: for each edge in bucket, acc[dst] += ex * xt[loc]
    uint32_t key = (graph * NT + tile) * RR + r;
    uint32_t beg = g_off[key], end = g_off[key + 1];
    float* accg = g_acc + (size_t)graph * NN * HD;
    for (uint32_t e = beg + wid; e < end; e += 8) {
        uint2 pk = g_es[e];
        int dst = pk.x & 0xffff;
        int loc = (pk.x >> 16) & 0x7f;
        float ex = __uint_as_float(pk.y);
        float4 v = *(float4*)&XS[loc * SA + lane * 4];
        v.x *= ex; v.y *= ex; v.z *= ex; v.w *= ex;
        float* p = accg + (size_t)dst * HD + lane * 4;
        asm volatile("red.global.add.v4.f32 [%0], {%1,%2,%3,%4};"
                     :: "l"(p), "f"(v.x), "f"(v.y), "f"(v.z), "f"(v.w)
                     : "memory");
    }
}

// ---------------- out = relu(acc/denom + b) ---------------------------------
__global__ void epilogue_kernel(const float* __restrict__ b1,
                                const float* __restrict__ b2,
                                float* __restrict__ out) {
    int graph = blockIdx.y;
    const float* bias = graph ? b2 : b1;
    int i = blockIdx.x * blockDim.x + threadIdx.x;   // over NN*32 float4s
    if (i >= NN * 32) return;
    int n = i >> 5, c4 = i & 31;
    float inv = 1.0f / (g_denom[graph * NN + n] + 1e-16f);
    float4 v = ((const float4*)g_acc)[(size_t)graph * NN * 32 + i];
    float4 bb = ((const float4*)bias)[c4];
    v.x = fmaxf(v.x * inv + bb.x, 0.f);
    v.y = fmaxf(v.y * inv + bb.y, 0.f);
    v.z = fmaxf(v.z * inv + bb.z, 0.f);
    v.w = fmaxf(v.w * inv + bb.w, 0.f);
    ((float4*)out)[(size_t)graph * NN * 32 + i] = v;
}

// ---------------- driver ----------------------------------------------------
extern "C" void kernel_launch(void* const* d_in, const int* in_sizes, int n_in,
                              void* d_out, int out_size) {
    const float* x1  = (const float*)d_in[0];
    const int*   ei1 = (const int*)d_in[1];
    const int*   et1 = (const int*)d_in[2];
    const float* x2  = (const float*)d_in[3];
    const int*   ei2 = (const int*)d_in[4];
    const int*   et2 = (const int*)d_in[5];
    const float* W1  = (const float*)d_in[6];
    const float* q1  = (const float*)d_in[7];
    const float* k1  = (const float*)d_in[8];
    const float* b1  = (const float*)d_in[9];
    const float* W2  = (const float*)d_in[10];
    const float* q2  = (const float*)d_in[11];
    const float* k2  = (const float*)d_in[12];
    const float* b2  = (const float*)d_in[13];
    float* out = (float*)d_out;

    cudaFuncSetAttribute(xform_scatter,
                         cudaFuncAttributeMaxDynamicSharedMemorySize, FUSED_SMEM);

    prep_kernel<<<2048, 256>>>();
    wqwk_kernel<<<dim3((RR * HD) / 8, NG), 256>>>(W1, q1, k1, W2, q2, k2);
    table_kernel<<<dim3((NN + 7) / 8, NG), 256>>>(x1, x2);
    hist_kernel<<<dim3((EE + 4095) / 4096, NG), 256>>>(ei1, et1, ei2, et2);
    scan_kernel<<<1, 256>>>();
    reorder_kernel<<<dim3((EE + 255) / 256, NG), 256>>>(ei1, et1, ei2, et2);
    xform_scatter<<<dim3(NT, RR, NG), 256, FUSED_SMEM>>>(x1, x2, W1, W2);
    epilogue_kernel<<<dim3((NN * 32 + 255) / 256, NG), 256>>>(b1, b2, out);
}